// round 15
// baseline (speedup 1.0000x reference)
#include <cuda_runtime.h>
#include <cuda_fp16.h>
#include <cstdint>
#include <math.h>

#define BATCH 4
#define SEQ   8192
#define DMODEL 1024
#define NH    16
#define DK    64
#define QKVN  (3*DMODEL)
#define MTOT  (BATCH*SEQ)

// ---------------------------------------------------------------------------
// Scratch (__device__ globals; allocation-free rule)
// All GEMM operands single fp16; fp32 accumulation everywhere.
// ---------------------------------------------------------------------------
__device__ __half g_xh[(size_t)MTOT*DMODEL];     // x single fp16
__device__ __half g_qkh[(size_t)MTOT*QKVN];      // qkv fp16 (q,k activated)
__device__ __half g_ahi[(size_t)MTOT*DMODEL];    // attn single fp16
__device__ __half g_wqh[(size_t)QKVN*DMODEL];    // w_qkv^T single fp16
__device__ __half g_woh[(size_t)DMODEL*DMODEL];  // w_o^T single fp16
__device__ float g_kv[BATCH*NH*DK*DK];           // fp32 accum [bh][d][f]
__device__ __half g_kvh[BATCH*NH*DK*DK];         // kv single fp16 for attn B
__device__ float g_ksum[BATCH*NH*DK];

// ---------------------------------------------------------------------------
// Helpers (baseline PTX only: must assemble at target sm_103)
// ---------------------------------------------------------------------------
__device__ __forceinline__ uint32_t smem_u32(const void* p) {
    uint32_t a;
    asm("{ .reg .u64 t; cvta.to.shared.u64 t, %1; cvt.u32.u64 %0, t; }" : "=r"(a) : "l"(p));
    return a;
}
__device__ __forceinline__ void cp_async16(uint32_t saddr, const void* gaddr) {
    asm volatile("cp.async.cg.shared.global [%0], [%1], 16;" :: "r"(saddr), "l"(gaddr));
}
__device__ __forceinline__ void cp_commit() {
    asm volatile("cp.async.commit_group;" ::: "memory");
}
template<int N>
__device__ __forceinline__ void cp_wait() {
    asm volatile("cp.async.wait_group %0;" :: "n"(N) : "memory");
}
__device__ __forceinline__ void ldsm_x4(uint32_t* r, uint32_t addr) {
    asm volatile("ldmatrix.sync.aligned.m8n8.x4.shared.b16 {%0,%1,%2,%3}, [%4];"
        : "=r"(r[0]), "=r"(r[1]), "=r"(r[2]), "=r"(r[3]) : "r"(addr));
}
__device__ __forceinline__ void ldsm_x4_t(uint32_t* r, uint32_t addr) {
    asm volatile("ldmatrix.sync.aligned.m8n8.x4.trans.shared.b16 {%0,%1,%2,%3}, [%4];"
        : "=r"(r[0]), "=r"(r[1]), "=r"(r[2]), "=r"(r[3]) : "r"(addr));
}
__device__ __forceinline__ void mma_f16(float* c, const uint32_t* a, const uint32_t* b) {
    asm volatile(
        "mma.sync.aligned.m16n8k16.row.col.f32.f16.f16.f32 "
        "{%0,%1,%2,%3}, {%4,%5,%6,%7}, {%8,%9}, {%0,%1,%2,%3};"
        : "+f"(c[0]), "+f"(c[1]), "+f"(c[2]), "+f"(c[3])
        : "r"(a[0]), "r"(a[1]), "r"(a[2]), "r"(a[3]), "r"(b[0]), "r"(b[1]));
}

// ---------------------------------------------------------------------------
// Convert fp32 -> single fp16
// ---------------------------------------------------------------------------
__global__ void __launch_bounds__(256) cvt_kernel(
    const float* __restrict__ src, __half* __restrict__ dst, int n4)
{
    int i = blockIdx.x * 256 + threadIdx.x;
    if (i >= n4) return;
    float4 v = ((const float4*)src)[i];
    ushort4 hv;
    hv.x = __half_as_ushort(__float2half(v.x));
    hv.y = __half_as_ushort(__float2half(v.y));
    hv.z = __half_as_ushort(__float2half(v.z));
    hv.w = __half_as_ushort(__float2half(v.w));
    ((ushort4*)dst)[i] = hv;
}

// Transpose + round: w [K][N] fp32 -> wT [N][K] single fp16
__global__ void __launch_bounds__(256) tsingle_kernel(
    const float* __restrict__ w, __half* __restrict__ hi, int K, int N)
{
    int idx = blockIdx.x * 256 + threadIdx.x;
    if (idx >= K * N) return;
    int k = idx / N, n = idx - k * N;
    hi[(size_t)n * K + k] = __float2half(w[idx]);
}

// ---------------------------------------------------------------------------
// mma.sync fp16 1-term GEMM: C = A[M,K] @ B^T (both single fp16, [N][K] B).
// BM=BN=128, BK=32, 256 threads (8 warps 4m x 2n, warp tile 32x64),
// 4-stage cp.async pipeline, XOR-swizzled smem, 2 CTAs/SM.
// Software-pipelined fragments: ALL 12 ldsm of the buffer issue before any
// MMA (MLP=12 in the LSU queue; ldsm latency overlaps the 32-MMA stream).
// GEMM1 (ACT=1,SPLIT=1): elu+1 on cols<2048, output single fp16.
// GEMM2 (ACT=0,SPLIT=0): fp32 output.
// ---------------------------------------------------------------------------
#define TILE_B (128*64)            // 8192 B per operand tile
#define STAGE_B (2*TILE_B)         // A|B = 16384 B
#define OFF_A 0
#define OFF_B TILE_B
#define NSTAGE 4
#define HS_TOTAL (NSTAGE*STAGE_B)  // 65536 B

template<bool ACT, bool SPLIT>
__global__ void __launch_bounds__(256, 2)
hmma_kernel(const __half* __restrict__ A, const __half* __restrict__ B,
            float* __restrict__ Cf, __half* __restrict__ Chi, int ldc, int K)
{
    extern __shared__ __align__(128) char smem[];
    const uint32_t sbase = smem_u32(smem);
    const int tid = threadIdx.x;
    const int wid = tid >> 5, l = tid & 31;
    const int n0 = blockIdx.x * 128;
    const int m0 = blockIdx.y * 128;
    const int wm = (wid & 3) * 32;
    const int wn = (wid >> 2) * 64;

    const int lrow = tid >> 1;
    const int c0   = (tid & 1) * 2;
    const int lsw  = (lrow >> 1) & 3;
    const char* gA = (const char*)(A + (size_t)(m0 + lrow) * K);
    const char* gB = (const char*)(B + (size_t)(n0 + lrow) * K);
    const uint32_t sd0 = sbase + lrow * 64 + (uint32_t)((c0 ^ lsw) << 4);
    const uint32_t sd1 = sbase + lrow * 64 + (uint32_t)(((c0 + 1) ^ lsw) << 4);

    const int nkt = K >> 5;

    auto load_stage = [&](int kt, int buf) {
        const uint32_t bo = (uint32_t)(buf * STAGE_B);
        const int goff = kt * 64;
        cp_async16(sd0 + bo + OFF_A, gA + goff + c0 * 16);
        cp_async16(sd1 + bo + OFF_A, gA + goff + c0 * 16 + 16);
        cp_async16(sd0 + bo + OFF_B, gB + goff + c0 * 16);
        cp_async16(sd1 + bo + OFF_B, gB + goff + c0 * 16 + 16);
    };

    load_stage(0, 0); cp_commit();
    load_stage(1, 1); cp_commit();
    load_stage(2, 2); cp_commit();

    float acc[16][4];
    #pragma unroll
    for (int i = 0; i < 16; ++i)
        #pragma unroll
        for (int j = 0; j < 4; ++j) acc[i][j] = 0.0f;

    uint32_t aoff[2][2], boff[2][4];
    {
        const uint32_t caA = (uint32_t)(l >> 4);
        const uint32_t caB = (uint32_t)((l >> 3) & 1);
        #pragma unroll
        for (int mt = 0; mt < 2; ++mt) {
            const int r = wm + (l & 15) + mt * 16;
            const uint32_t sw = (uint32_t)((r >> 1) & 3);
            #pragma unroll
            for (int kk = 0; kk < 2; ++kk)
                aoff[kk][mt] = (uint32_t)(r * 64) + (((kk * 2 + caA) ^ sw) << 4);
        }
        #pragma unroll
        for (int ng = 0; ng < 4; ++ng) {
            const int r = wn + ((l >> 4) & 1) * 8 + (l & 7) + ng * 16;
            const uint32_t sw = (uint32_t)((r >> 1) & 3);
            #pragma unroll
            for (int kk = 0; kk < 2; ++kk)
                boff[kk][ng] = (uint32_t)(r * 64) + (((kk * 2 + caB) ^ sw) << 4);
        }
    }

    int buf = 0, lbuf = NSTAGE - 1;
    #pragma unroll 1
    for (int kt = 0; kt < nkt; ++kt) {
        cp_wait<NSTAGE - 2>();
        __syncthreads();
        if (kt + NSTAGE - 1 < nkt) { load_stage(kt + NSTAGE - 1, lbuf); }
        cp_commit();

        const uint32_t sb = sbase + buf * STAGE_B;
        // ---- issue ALL fragment loads for both k16 sub-steps first ----
        uint32_t ah[2][2][4], bh[2][4][4];
        #pragma unroll
        for (int kk = 0; kk < 2; ++kk)
            #pragma unroll
            for (int mt = 0; mt < 2; ++mt)
                ldsm_x4(ah[kk][mt], sb + OFF_A + aoff[kk][mt]);
        #pragma unroll
        for (int kk = 0; kk < 2; ++kk)
            #pragma unroll
            for (int ng = 0; ng < 4; ++ng)
                ldsm_x4(bh[kk][ng], sb + OFF_B + boff[kk][ng]);
        // ---- then the 32 MMAs ----
        #pragma unroll
        for (int kk = 0; kk < 2; ++kk)
            #pragma unroll
            for (int mt = 0; mt < 2; ++mt)
                #pragma unroll
                for (int nt = 0; nt < 8; ++nt)
                    mma_f16(acc[mt * 8 + nt], ah[kk][mt], &bh[kk][nt >> 1][(nt & 1) * 2]);

        buf  = (buf  == NSTAGE - 1) ? 0 : buf + 1;
        lbuf = (lbuf == NSTAGE - 1) ? 0 : lbuf + 1;
    }

    const bool doact = ACT && (n0 < 2048);
    const int erow = m0 + wm + (l >> 2);
    const int ecol = n0 + wn + (l & 3) * 2;
    #pragma unroll
    for (int mt = 0; mt < 2; ++mt)
        #pragma unroll
        for (int nt = 0; nt < 8; ++nt) {
            float v0 = acc[mt*8+nt][0], v1 = acc[mt*8+nt][1];
            float v2 = acc[mt*8+nt][2], v3 = acc[mt*8+nt][3];
            if (doact) {
                v0 = (v0 > 0.f) ? v0 + 1.f : expf(v0);
                v1 = (v1 > 0.f) ? v1 + 1.f : expf(v1);
                v2 = (v2 > 0.f) ? v2 + 1.f : expf(v2);
                v3 = (v3 > 0.f) ? v3 + 1.f : expf(v3);
            }
            const int r = erow + mt * 16;
            const int cc = ecol + nt * 8;
            if (SPLIT) {
                ushort2 h0, h1;
                h0.x = __half_as_ushort(__float2half(v0));
                h0.y = __half_as_ushort(__float2half(v1));
                h1.x = __half_as_ushort(__float2half(v2));
                h1.y = __half_as_ushort(__float2half(v3));
                *(ushort2*)(Chi + (size_t)r * ldc + cc) = h0;
                *(ushort2*)(Chi + (size_t)(r + 8) * ldc + cc) = h1;
            } else {
                float2 o0; o0.x = v0; o0.y = v1;
                float2 o1; o1.x = v2; o1.y = v3;
                *(float2*)(Cf + (size_t)r * ldc + cc) = o0;
                *(float2*)(Cf + (size_t)(r + 8) * ldc + cc) = o1;
            }
        }
}

// ---------------------------------------------------------------------------
// Zero kv/ksum accumulators
// ---------------------------------------------------------------------------
__global__ void zero_kv_kernel() {
    int i = blockIdx.x * 256 + threadIdx.x;
    if (i < BATCH*NH*DK*DK) g_kv[i] = 0.0f;
    if (i < BATCH*NH*DK)    g_ksum[i] = 0.0f;
}

// ---------------------------------------------------------------------------
// kv GEMM (tensor): C[bh][d][f] += k^T @ v over 512-row split; ksum SIMT.
// ---------------------------------------------------------------------------
#define KV_TILE_B (64*128)          // 8192
#define KV_STAGE_B (2*KV_TILE_B)    // k|v = 16384
#define KV_SMEM (2*KV_STAGE_B)      // 32768

__global__ void __launch_bounds__(256, 2) kv_tc_kernel()
{
    extern __shared__ __align__(128) char smem[];
    const uint32_t sbase = smem_u32(smem);
    const int tid = threadIdx.x;
    const int wid = tid >> 5, l = tid & 31;
    const int bh = blockIdx.x;
    const int b = bh >> 4, h = bh & 15;
    const int n0 = blockIdx.y * 512;
    const int wm = (wid & 1) * 32;      // d offset
    const int wn = (wid >> 1) * 16;     // f offset

    const int lrow = tid >> 2;
    const int lc0 = (tid & 3) * 2;
    const uint32_t sw0 = (uint32_t)((lc0 ^ (lrow & 7)) << 4);
    const uint32_t sw1 = (uint32_t)(((lc0 + 1) ^ (lrow & 7)) << 4);
    const uint32_t sdr = sbase + (uint32_t)(lrow * 128);

    auto load_chunk = [&](int c, int buf) {
        const size_t gr = (size_t)(b*SEQ + n0 + c*64 + lrow) * QKVN + h*64;
        const __half* srcK = g_qkh + gr + 1024;
        const __half* srcV = g_qkh + gr + 2048;
        const uint32_t sb = sdr + buf * KV_STAGE_B;
        cp_async16(sb + sw0, srcK + lc0*8);
        cp_async16(sb + sw1, srcK + lc0*8 + 8);
        cp_async16(sb + KV_TILE_B + sw0, srcV + lc0*8);
        cp_async16(sb + KV_TILE_B + sw1, srcV + lc0*8 + 8);
    };

    uint32_t aoff[2], boff;
    {
        const int arow = (l & 7) + ((l >> 4) & 1) * 8;
        #pragma unroll
        for (int mt = 0; mt < 2; ++mt) {
            const uint32_t ach = (uint32_t)((wm >> 3) + mt * 2 + ((l >> 3) & 1));
            aoff[mt] = (uint32_t)(arow * 128) + ((ach ^ (uint32_t)(l & 7)) << 4);
        }
        const int brow = (l & 7) + ((l >> 3) & 1) * 8;
        const uint32_t bch = (uint32_t)((wn >> 3) + ((l >> 4) & 1));
        boff = (uint32_t)(brow * 128) + ((bch ^ (uint32_t)(l & 7)) << 4);
    }

    float acc[4][4];
    #pragma unroll
    for (int i = 0; i < 4; ++i)
        #pragma unroll
        for (int j = 0; j < 4; ++j) acc[i][j] = 0.0f;
    float ksacc = 0.0f;
    const int kd = tid & 63;
    const int kr0 = (tid >> 6) * 16;

    load_chunk(0, 0); cp_commit();

    #pragma unroll 1
    for (int c = 0; c < 8; ++c) {
        cp_wait<0>();
        __syncthreads();
        if (c < 7) { load_chunk(c + 1, (c + 1) & 1); }
        cp_commit();

        const int bufo = (c & 1) * KV_STAGE_B;
        const uint32_t sb = sbase + bufo;

        #pragma unroll
        for (int i = 0; i < 16; ++i) {
            const int row = kr0 + i;
            const int off = bufo + row*128 + (((kd >> 3) ^ (row & 7)) << 4) + (kd & 7)*2;
            ksacc += __half2float(*(const __half*)(smem + off));
        }

        #pragma unroll
        for (int ks = 0; ks < 4; ++ks) {
            const uint32_t ko = (uint32_t)(ks * 2048);
            uint32_t ah[2][4], bhf[4];
            #pragma unroll
            for (int mt = 0; mt < 2; ++mt)
                ldsm_x4_t(ah[mt], sb + ko + aoff[mt]);
            ldsm_x4_t(bhf, sb + KV_TILE_B + ko + boff);
            #pragma unroll
            for (int mt = 0; mt < 2; ++mt)
                #pragma unroll
                for (int ng = 0; ng < 2; ++ng)
                    mma_f16(acc[mt*2+ng], ah[mt], &bhf[ng*2]);
        }
    }

    #pragma unroll
    for (int mt = 0; mt < 2; ++mt)
        #pragma unroll
        for (int ng = 0; ng < 2; ++ng) {
            const int t = mt*2 + ng;
            const int d = wm + mt*16 + (l >> 2);
            const int f = wn + ng*8 + (l & 3)*2;
            float* dst = g_kv + ((size_t)bh*DK + d)*DK + f;
            atomicAdd(dst,     acc[t][0]);
            atomicAdd(dst + 1, acc[t][1]);
            float* dst2 = dst + 8*DK;
            atomicAdd(dst2,     acc[t][2]);
            atomicAdd(dst2 + 1, acc[t][3]);
        }
    atomicAdd(g_ksum + bh*DK + kd, ksacc);
}

// Round g_kv -> single fp16 for attn B operand
__global__ void __launch_bounds__(256) kvsplit_kernel() {
    int i = blockIdx.x * 256 + threadIdx.x;
    if (i >= BATCH*NH*DK*DK) return;
    g_kvh[i] = __float2half(g_kv[i]);
}

// ---------------------------------------------------------------------------
// attn GEMM (tensor): attn[n,f] = (q @ kv) / (q . ksum + 1e-6)
// ---------------------------------------------------------------------------
#define AT_Q 0
#define AT_KV 16384
#define AT_KSUM 24576
#define AT_DENS 24832
#define AT_SMEM 25344

__global__ void __launch_bounds__(256, 2) attn_tc_kernel()
{
    extern __shared__ __align__(128) char smem[];
    const uint32_t sbase = smem_u32(smem);
    float* ksum_s = (float*)(smem + AT_KSUM);
    float* dens_s = (float*)(smem + AT_DENS);
    const int tid = threadIdx.x;
    const int wid = tid >> 5, l = tid & 31;
    const int n0 = blockIdx.x * 128;
    const int bh = blockIdx.y;
    const int b = bh >> 4, hh = bh & 15;
    const int wm = (wid & 3) * 32;
    const int wn = (wid >> 2) * 32;

    {
        const int qrow = tid >> 1;
        const int qc0 = (tid & 1) * 4;
        const size_t gq = (size_t)(b*SEQ + n0 + qrow) * QKVN + hh*64;
        #pragma unroll
        for (int j = 0; j < 4; ++j) {
            const int c = qc0 + j;
            const uint32_t ph = (uint32_t)((c ^ (qrow & 7)) << 4);
            cp_async16(sbase + AT_Q + qrow*128 + ph, g_qkh + gq + c*8);
        }
        const int kvrow = tid >> 2;
        const int kc0 = (tid & 3) * 2;
        const size_t gkv = (size_t)bh*DK*DK + kvrow*64;
        #pragma unroll
        for (int j = 0; j < 2; ++j) {
            const int c = kc0 + j;
            const uint32_t ph = (uint32_t)((c ^ (kvrow & 7)) << 4);
            cp_async16(sbase + AT_KV + kvrow*128 + ph, g_kvh + gkv + c*8);
        }
        if (tid < 64) ksum_s[tid] = g_ksum[bh*DK + tid];
        cp_commit();
        cp_wait<0>();
        __syncthreads();
    }

    if (tid < 128) {
        const int row = tid;
        float s = 0.0f;
        #pragma unroll 16
        for (int d = 0; d < 64; ++d) {
            const int off = row*128 + (((d >> 3) ^ (row & 7)) << 4) + (d & 7)*2;
            s += __half2float(*(const __half*)(smem + AT_Q + off)) * ksum_s[d];
        }
        dens_s[row] = s + 1e-6f;
    }
    __syncthreads();

    int arow[2]; uint32_t aswz[2];
    #pragma unroll
    for (int mt = 0; mt < 2; ++mt) {
        arow[mt] = wm + (l & 15) + mt*16;
        aswz[mt] = (uint32_t)(arow[mt] & 7);
    }
    uint32_t boff[2];
    {
        const int brow = (l & 7) + ((l >> 3) & 1) * 8;
        #pragma unroll
        for (int ng = 0; ng < 2; ++ng) {
            const uint32_t bch = (uint32_t)((wn >> 3) + ng*2 + ((l >> 4) & 1));
            boff[ng] = (uint32_t)(brow * 128) + ((bch ^ (uint32_t)(l & 7)) << 4);
        }
    }

    float acc[8][4];
    #pragma unroll
    for (int i = 0; i < 8; ++i)
        #pragma unroll
        for (int j = 0; j < 4; ++j) acc[i][j] = 0.0f;

    #pragma unroll
    for (int ks = 0; ks < 4; ++ks) {
        uint32_t ah[2][4], bhf[2][4];
        #pragma unroll
        for (int mt = 0; mt < 2; ++mt) {
            const uint32_t ach = (uint32_t)(ks*2 + (l >> 4));
            const uint32_t ao = (uint32_t)(arow[mt]*128) + ((ach ^ aswz[mt]) << 4);
            ldsm_x4(ah[mt], sbase + AT_Q + ao);
        }
        #pragma unroll
        for (int ng = 0; ng < 2; ++ng) {
            const uint32_t ko = (uint32_t)(ks * 2048);
            ldsm_x4_t(bhf[ng], sbase + AT_KV + ko + boff[ng]);
        }
        #pragma unroll
        for (int mt = 0; mt < 2; ++mt)
            #pragma unroll
            for (int g = 0; g < 4; ++g)
                mma_f16(acc[mt*4+g], ah[mt], &bhf[g >> 1][(g & 1)*2]);
    }

    #pragma unroll
    for (int mt = 0; mt < 2; ++mt)
        #pragma unroll
        for (int g = 0; g < 4; ++g) {
            const int t = mt*4 + g;
            const int lr = wm + mt*16 + (l >> 2);
            const int f = wn + g*8 + (l & 3)*2;
            const float inv1 = 1.0f / dens_s[lr];
            const float inv2 = 1.0f / dens_s[lr + 8];
            ushort2 h0, h1;
            h0.x = __half_as_ushort(__float2half(acc[t][0]*inv1));
            h0.y = __half_as_ushort(__float2half(acc[t][1]*inv1));
            h1.x = __half_as_ushort(__float2half(acc[t][2]*inv2));
            h1.y = __half_as_ushort(__float2half(acc[t][3]*inv2));
            const size_t o1 = (size_t)(b*SEQ + n0 + lr) * DMODEL + hh*64 + f;
            const size_t o2 = o1 + (size_t)8 * DMODEL;
            *(ushort2*)(g_ahi + o1) = h0;
            *(ushort2*)(g_ahi + o2) = h1;
        }
}

// ---------------------------------------------------------------------------
extern "C" void kernel_launch(void* const* d_in, const int* in_sizes, int n_in,
                              void* d_out, int out_size)
{
    const float* x    = (const float*)d_in[0];
    const float* wqkv = (const float*)d_in[1];
    const float* wo   = (const float*)d_in[2];
    float* out = (float*)d_out;

    __half *xh, *ahi, *wqh, *woh, *qkh;
    cudaGetSymbolAddress((void**)&xh, g_xh);
    cudaGetSymbolAddress((void**)&ahi, g_ahi);
    cudaGetSymbolAddress((void**)&wqh, g_wqh);
    cudaGetSymbolAddress((void**)&woh, g_woh);
    cudaGetSymbolAddress((void**)&qkh, g_qkh);

    cudaFuncSetAttribute(hmma_kernel<true, true>,
        cudaFuncAttributeMaxDynamicSharedMemorySize, HS_TOTAL);
    cudaFuncSetAttribute(hmma_kernel<false, false>,
        cudaFuncAttributeMaxDynamicSharedMemorySize, HS_TOTAL);
    cudaFuncSetAttribute(kv_tc_kernel,
        cudaFuncAttributeMaxDynamicSharedMemorySize, KV_SMEM);
    cudaFuncSetAttribute(attn_tc_kernel,
        cudaFuncAttributeMaxDynamicSharedMemorySize, AT_SMEM);

    // 1) convert x to single fp16; weights to single fp16 (transposed)
    {
        int n4 = MTOT * DMODEL / 4;
        cvt_kernel<<<(n4 + 255)/256, 256>>>(x, xh, n4);
    }
    tsingle_kernel<<<(DMODEL*QKVN + 255)/256, 256>>>(wqkv, wqh, DMODEL, QKVN);
    tsingle_kernel<<<(DMODEL*DMODEL + 255)/256, 256>>>(wo, woh, DMODEL, DMODEL);

    // 2) QKV projection (1-term); epilogue: elu+1 on q,k; single fp16 out
    hmma_kernel<true, true><<<dim3(QKVN/128, MTOT/128), 256, HS_TOTAL>>>(
        xh, wqh, nullptr, qkh, QKVN, DMODEL);

    // 3) zero accumulators
    zero_kv_kernel<<<(BATCH*NH*DK*DK + 255)/256, 256>>>();

    // 4) kv = k^T v (+ksum) via tensor cores, split-K atomics
    kv_tc_kernel<<<dim3(BATCH*NH, 16), 256, KV_SMEM>>>();

    // 5) round kv to single fp16
    kvsplit_kernel<<<(BATCH*NH*DK*DK + 255)/256, 256>>>();

    // 6) attn = (q @ kv) / (q . ksum + 1e-6) -> single fp16
    attn_tc_kernel<<<dim3(SEQ/128, BATCH*NH), 256, AT_SMEM>>>();

    // 7) output projection (1-term)
    hmma_kernel<false, false><<<dim3(DMODEL/128, MTOT/128), 256, HS_TOTAL>>>(
        ahi, woh, out, nullptr, DMODEL, DMODEL);
}

// round 16
// speedup vs baseline: 1.0030x; 1.0030x over previous
#include <cuda_runtime.h>
#include <cuda_fp16.h>
#include <cstdint>
#include <math.h>

#define BATCH 4
#define SEQ   8192
#define DMODEL 1024
#define NH    16
#define DK    64
#define QKVN  (3*DMODEL)
#define MTOT  (BATCH*SEQ)

// ---------------------------------------------------------------------------
// Scratch (__device__ globals; allocation-free rule)
// All GEMM operands single fp16; fp32 accumulation everywhere.
// ---------------------------------------------------------------------------
__device__ __half g_xh[(size_t)MTOT*DMODEL];     // x single fp16
__device__ __half g_qkh[(size_t)MTOT*QKVN];      // qkv fp16 (q,k activated)
__device__ __half g_ahi[(size_t)MTOT*DMODEL];    // attn single fp16
__device__ __half g_wqh[(size_t)QKVN*DMODEL];    // w_qkv^T single fp16
__device__ __half g_woh[(size_t)DMODEL*DMODEL];  // w_o^T single fp16
__device__ float g_kv[BATCH*NH*DK*DK];           // fp32 accum [bh][d][f]
__device__ float g_ksum[BATCH*NH*DK];

// ---------------------------------------------------------------------------
// Helpers (baseline PTX only: must assemble at target sm_103)
// ---------------------------------------------------------------------------
__device__ __forceinline__ uint32_t smem_u32(const void* p) {
    uint32_t a;
    asm("{ .reg .u64 t; cvta.to.shared.u64 t, %1; cvt.u32.u64 %0, t; }" : "=r"(a) : "l"(p));
    return a;
}
__device__ __forceinline__ void cp_async16(uint32_t saddr, const void* gaddr) {
    asm volatile("cp.async.cg.shared.global [%0], [%1], 16;" :: "r"(saddr), "l"(gaddr));
}
__device__ __forceinline__ void cp_commit() {
    asm volatile("cp.async.commit_group;" ::: "memory");
}
template<int N>
__device__ __forceinline__ void cp_wait() {
    asm volatile("cp.async.wait_group %0;" :: "n"(N) : "memory");
}
__device__ __forceinline__ void ldsm_x4(uint32_t* r, uint32_t addr) {
    asm volatile("ldmatrix.sync.aligned.m8n8.x4.shared.b16 {%0,%1,%2,%3}, [%4];"
        : "=r"(r[0]), "=r"(r[1]), "=r"(r[2]), "=r"(r[3]) : "r"(addr));
}
__device__ __forceinline__ void ldsm_x4_t(uint32_t* r, uint32_t addr) {
    asm volatile("ldmatrix.sync.aligned.m8n8.x4.trans.shared.b16 {%0,%1,%2,%3}, [%4];"
        : "=r"(r[0]), "=r"(r[1]), "=r"(r[2]), "=r"(r[3]) : "r"(addr));
}
__device__ __forceinline__ void mma_f16(float* c, const uint32_t* a, const uint32_t* b) {
    asm volatile(
        "mma.sync.aligned.m16n8k16.row.col.f32.f16.f16.f32 "
        "{%0,%1,%2,%3}, {%4,%5,%6,%7}, {%8,%9}, {%0,%1,%2,%3};"
        : "+f"(c[0]), "+f"(c[1]), "+f"(c[2]), "+f"(c[3])
        : "r"(a[0]), "r"(a[1]), "r"(a[2]), "r"(a[3]), "r"(b[0]), "r"(b[1]));
}

// ---------------------------------------------------------------------------
// Convert fp32 -> single fp16
// ---------------------------------------------------------------------------
__global__ void __launch_bounds__(256) cvt_kernel(
    const float* __restrict__ src, __half* __restrict__ dst, int n4)
{
    int i = blockIdx.x * 256 + threadIdx.x;
    if (i >= n4) return;
    float4 v = ((const float4*)src)[i];
    ushort4 hv;
    hv.x = __half_as_ushort(__float2half(v.x));
    hv.y = __half_as_ushort(__float2half(v.y));
    hv.z = __half_as_ushort(__float2half(v.z));
    hv.w = __half_as_ushort(__float2half(v.w));
    ((ushort4*)dst)[i] = hv;
}

// Transpose + round: w [K][N] fp32 -> wT [N][K] single fp16
__global__ void __launch_bounds__(256) tsingle_kernel(
    const float* __restrict__ w, __half* __restrict__ hi, int K, int N)
{
    int idx = blockIdx.x * 256 + threadIdx.x;
    if (idx >= K * N) return;
    int k = idx / N, n = idx - k * N;
    hi[(size_t)n * K + k] = __float2half(w[idx]);
}

// ---------------------------------------------------------------------------
// mma.sync fp16 1-term GEMM: C = A[M,K] @ B^T (both single fp16, [N][K] B).
// BM=BN=128, BK=32, 256 threads (8 warps 4m x 2n, warp tile 32x64),
// 4-stage cp.async pipeline, XOR-swizzled smem, 2 CTAs/SM.   [R14 config]
// GEMM1 (ACT=1,SPLIT=1): elu+1 on cols<2048, output single fp16.
// GEMM2 (ACT=0,SPLIT=0): fp32 output.
// ---------------------------------------------------------------------------
#define TILE_B (128*64)            // 8192 B per operand tile
#define STAGE_B (2*TILE_B)         // A|B = 16384 B
#define OFF_A 0
#define OFF_B TILE_B
#define NSTAGE 4
#define HS_TOTAL (NSTAGE*STAGE_B)  // 65536 B

template<bool ACT, bool SPLIT>
__global__ void __launch_bounds__(256, 2)
hmma_kernel(const __half* __restrict__ A, const __half* __restrict__ B,
            float* __restrict__ Cf, __half* __restrict__ Chi, int ldc, int K)
{
    extern __shared__ __align__(128) char smem[];
    const uint32_t sbase = smem_u32(smem);
    const int tid = threadIdx.x;
    const int wid = tid >> 5, l = tid & 31;
    const int n0 = blockIdx.x * 128;
    const int m0 = blockIdx.y * 128;
    const int wm = (wid & 3) * 32;
    const int wn = (wid >> 2) * 64;

    const int lrow = tid >> 1;
    const int c0   = (tid & 1) * 2;
    const int lsw  = (lrow >> 1) & 3;
    const char* gA = (const char*)(A + (size_t)(m0 + lrow) * K);
    const char* gB = (const char*)(B + (size_t)(n0 + lrow) * K);
    const uint32_t sd0 = sbase + lrow * 64 + (uint32_t)((c0 ^ lsw) << 4);
    const uint32_t sd1 = sbase + lrow * 64 + (uint32_t)(((c0 + 1) ^ lsw) << 4);

    const int nkt = K >> 5;

    auto load_stage = [&](int kt, int buf) {
        const uint32_t bo = (uint32_t)(buf * STAGE_B);
        const int goff = kt * 64;
        cp_async16(sd0 + bo + OFF_A, gA + goff + c0 * 16);
        cp_async16(sd1 + bo + OFF_A, gA + goff + c0 * 16 + 16);
        cp_async16(sd0 + bo + OFF_B, gB + goff + c0 * 16);
        cp_async16(sd1 + bo + OFF_B, gB + goff + c0 * 16 + 16);
    };

    load_stage(0, 0); cp_commit();
    load_stage(1, 1); cp_commit();
    load_stage(2, 2); cp_commit();

    float acc[16][4];
    #pragma unroll
    for (int i = 0; i < 16; ++i)
        #pragma unroll
        for (int j = 0; j < 4; ++j) acc[i][j] = 0.0f;

    uint32_t aoff[2][2], boff[2][4];
    {
        const uint32_t caA = (uint32_t)(l >> 4);
        const uint32_t caB = (uint32_t)((l >> 3) & 1);
        #pragma unroll
        for (int mt = 0; mt < 2; ++mt) {
            const int r = wm + (l & 15) + mt * 16;
            const uint32_t sw = (uint32_t)((r >> 1) & 3);
            #pragma unroll
            for (int kk = 0; kk < 2; ++kk)
                aoff[kk][mt] = (uint32_t)(r * 64) + (((kk * 2 + caA) ^ sw) << 4);
        }
        #pragma unroll
        for (int ng = 0; ng < 4; ++ng) {
            const int r = wn + ((l >> 4) & 1) * 8 + (l & 7) + ng * 16;
            const uint32_t sw = (uint32_t)((r >> 1) & 3);
            #pragma unroll
            for (int kk = 0; kk < 2; ++kk)
                boff[kk][ng] = (uint32_t)(r * 64) + (((kk * 2 + caB) ^ sw) << 4);
        }
    }

    int buf = 0, lbuf = NSTAGE - 1;
    #pragma unroll 1
    for (int kt = 0; kt < nkt; ++kt) {
        cp_wait<NSTAGE - 2>();
        __syncthreads();
        if (kt + NSTAGE - 1 < nkt) { load_stage(kt + NSTAGE - 1, lbuf); }
        cp_commit();

        const uint32_t sb = sbase + buf * STAGE_B;
        #pragma unroll
        for (int kk = 0; kk < 2; ++kk) {
            uint32_t ah[2][4], bh[4][4];
            #pragma unroll
            for (int mt = 0; mt < 2; ++mt)
                ldsm_x4(ah[mt], sb + OFF_A + aoff[kk][mt]);
            #pragma unroll
            for (int ng = 0; ng < 4; ++ng)
                ldsm_x4(bh[ng], sb + OFF_B + boff[kk][ng]);
            #pragma unroll
            for (int mt = 0; mt < 2; ++mt)
                #pragma unroll
                for (int nt = 0; nt < 8; ++nt)
                    mma_f16(acc[mt * 8 + nt], ah[mt], &bh[nt >> 1][(nt & 1) * 2]);
        }
        buf  = (buf  == NSTAGE - 1) ? 0 : buf + 1;
        lbuf = (lbuf == NSTAGE - 1) ? 0 : lbuf + 1;
    }

    const bool doact = ACT && (n0 < 2048);
    const int erow = m0 + wm + (l >> 2);
    const int ecol = n0 + wn + (l & 3) * 2;
    #pragma unroll
    for (int mt = 0; mt < 2; ++mt)
        #pragma unroll
        for (int nt = 0; nt < 8; ++nt) {
            float v0 = acc[mt*8+nt][0], v1 = acc[mt*8+nt][1];
            float v2 = acc[mt*8+nt][2], v3 = acc[mt*8+nt][3];
            if (doact) {
                v0 = (v0 > 0.f) ? v0 + 1.f : expf(v0);
                v1 = (v1 > 0.f) ? v1 + 1.f : expf(v1);
                v2 = (v2 > 0.f) ? v2 + 1.f : expf(v2);
                v3 = (v3 > 0.f) ? v3 + 1.f : expf(v3);
            }
            const int r = erow + mt * 16;
            const int cc = ecol + nt * 8;
            if (SPLIT) {
                ushort2 h0, h1;
                h0.x = __half_as_ushort(__float2half(v0));
                h0.y = __half_as_ushort(__float2half(v1));
                h1.x = __half_as_ushort(__float2half(v2));
                h1.y = __half_as_ushort(__float2half(v3));
                *(ushort2*)(Chi + (size_t)r * ldc + cc) = h0;
                *(ushort2*)(Chi + (size_t)(r + 8) * ldc + cc) = h1;
            } else {
                float2 o0; o0.x = v0; o0.y = v1;
                float2 o1; o1.x = v2; o1.y = v3;
                *(float2*)(Cf + (size_t)r * ldc + cc) = o0;
                *(float2*)(Cf + (size_t)(r + 8) * ldc + cc) = o1;
            }
        }
}

// ---------------------------------------------------------------------------
// Zero kv/ksum accumulators
// ---------------------------------------------------------------------------
__global__ void zero_kv_kernel() {
    int i = blockIdx.x * 256 + threadIdx.x;
    if (i < BATCH*NH*DK*DK) g_kv[i] = 0.0f;
    if (i < BATCH*NH*DK)    g_ksum[i] = 0.0f;
}

// ---------------------------------------------------------------------------
// kv GEMM (tensor): C[bh][d][f] += k^T @ v over 512-row split; ksum SIMT.
// ---------------------------------------------------------------------------
#define KV_TILE_B (64*128)          // 8192
#define KV_STAGE_B (2*KV_TILE_B)    // k|v = 16384
#define KV_SMEM (2*KV_STAGE_B)      // 32768

__global__ void __launch_bounds__(256, 2) kv_tc_kernel()
{
    extern __shared__ __align__(128) char smem[];
    const uint32_t sbase = smem_u32(smem);
    const int tid = threadIdx.x;
    const int wid = tid >> 5, l = tid & 31;
    const int bh = blockIdx.x;
    const int b = bh >> 4, h = bh & 15;
    const int n0 = blockIdx.y * 512;
    const int wm = (wid & 1) * 32;      // d offset
    const int wn = (wid >> 1) * 16;     // f offset

    const int lrow = tid >> 2;
    const int lc0 = (tid & 3) * 2;
    const uint32_t sw0 = (uint32_t)((lc0 ^ (lrow & 7)) << 4);
    const uint32_t sw1 = (uint32_t)(((lc0 + 1) ^ (lrow & 7)) << 4);
    const uint32_t sdr = sbase + (uint32_t)(lrow * 128);

    auto load_chunk = [&](int c, int buf) {
        const size_t gr = (size_t)(b*SEQ + n0 + c*64 + lrow) * QKVN + h*64;
        const __half* srcK = g_qkh + gr + 1024;
        const __half* srcV = g_qkh + gr + 2048;
        const uint32_t sb = sdr + buf * KV_STAGE_B;
        cp_async16(sb + sw0, srcK + lc0*8);
        cp_async16(sb + sw1, srcK + lc0*8 + 8);
        cp_async16(sb + KV_TILE_B + sw0, srcV + lc0*8);
        cp_async16(sb + KV_TILE_B + sw1, srcV + lc0*8 + 8);
    };

    uint32_t aoff[2], boff;
    {
        const int arow = (l & 7) + ((l >> 4) & 1) * 8;
        #pragma unroll
        for (int mt = 0; mt < 2; ++mt) {
            const uint32_t ach = (uint32_t)((wm >> 3) + mt * 2 + ((l >> 3) & 1));
            aoff[mt] = (uint32_t)(arow * 128) + ((ach ^ (uint32_t)(l & 7)) << 4);
        }
        const int brow = (l & 7) + ((l >> 3) & 1) * 8;
        const uint32_t bch = (uint32_t)((wn >> 3) + ((l >> 4) & 1));
        boff = (uint32_t)(brow * 128) + ((bch ^ (uint32_t)(l & 7)) << 4);
    }

    float acc[4][4];
    #pragma unroll
    for (int i = 0; i < 4; ++i)
        #pragma unroll
        for (int j = 0; j < 4; ++j) acc[i][j] = 0.0f;
    float ksacc = 0.0f;
    const int kd = tid & 63;
    const int kr0 = (tid >> 6) * 16;

    load_chunk(0, 0); cp_commit();

    #pragma unroll 1
    for (int c = 0; c < 8; ++c) {
        cp_wait<0>();
        __syncthreads();
        if (c < 7) { load_chunk(c + 1, (c + 1) & 1); }
        cp_commit();

        const int bufo = (c & 1) * KV_STAGE_B;
        const uint32_t sb = sbase + bufo;

        #pragma unroll
        for (int i = 0; i < 16; ++i) {
            const int row = kr0 + i;
            const int off = bufo + row*128 + (((kd >> 3) ^ (row & 7)) << 4) + (kd & 7)*2;
            ksacc += __half2float(*(const __half*)(smem + off));
        }

        #pragma unroll
        for (int ks = 0; ks < 4; ++ks) {
            const uint32_t ko = (uint32_t)(ks * 2048);
            uint32_t ah[2][4], bhf[4];
            #pragma unroll
            for (int mt = 0; mt < 2; ++mt)
                ldsm_x4_t(ah[mt], sb + ko + aoff[mt]);
            ldsm_x4_t(bhf, sb + KV_TILE_B + ko + boff);
            #pragma unroll
            for (int mt = 0; mt < 2; ++mt)
                #pragma unroll
                for (int ng = 0; ng < 2; ++ng)
                    mma_f16(acc[mt*2+ng], ah[mt], &bhf[ng*2]);
        }
    }

    #pragma unroll
    for (int mt = 0; mt < 2; ++mt)
        #pragma unroll
        for (int ng = 0; ng < 2; ++ng) {
            const int t = mt*2 + ng;
            const int d = wm + mt*16 + (l >> 2);
            const int f = wn + ng*8 + (l & 3)*2;
            float* dst = g_kv + ((size_t)bh*DK + d)*DK + f;
            atomicAdd(dst,     acc[t][0]);
            atomicAdd(dst + 1, acc[t][1]);
            float* dst2 = dst + 8*DK;
            atomicAdd(dst2,     acc[t][2]);
            atomicAdd(dst2 + 1, acc[t][3]);
        }
    atomicAdd(g_ksum + bh*DK + kd, ksacc);
}

// ---------------------------------------------------------------------------
// attn GEMM (tensor): attn[n,f] = (q @ kv) / (q . ksum + 1e-6)
// kv loaded fp32 from g_kv and converted to fp16 during smem staging
// (kvsplit kernel folded in; g_kv is L2-hot: 16KB per bh).
// ---------------------------------------------------------------------------
#define AT_Q 0
#define AT_KV 16384
#define AT_KSUM 24576
#define AT_DENS 24832
#define AT_SMEM 25344

__global__ void __launch_bounds__(256, 2) attn_tc_kernel()
{
    extern __shared__ __align__(128) char smem[];
    const uint32_t sbase = smem_u32(smem);
    float* ksum_s = (float*)(smem + AT_KSUM);
    float* dens_s = (float*)(smem + AT_DENS);
    const int tid = threadIdx.x;
    const int wid = tid >> 5, l = tid & 31;
    const int n0 = blockIdx.x * 128;
    const int bh = blockIdx.y;
    const int b = bh >> 4, hh = bh & 15;
    const int wm = (wid & 3) * 32;
    const int wn = (wid >> 2) * 32;

    {
        // q tile via cp.async (fp16 source)
        const int qrow = tid >> 1;
        const int qc0 = (tid & 1) * 4;
        const size_t gq = (size_t)(b*SEQ + n0 + qrow) * QKVN + hh*64;
        #pragma unroll
        for (int j = 0; j < 4; ++j) {
            const int c = qc0 + j;
            const uint32_t ph = (uint32_t)((c ^ (qrow & 7)) << 4);
            cp_async16(sbase + AT_Q + qrow*128 + ph, g_qkh + gq + c*8);
        }
        cp_commit();

        // kv tile: load fp32, convert to fp16, store swizzled (fold of kvsplit)
        const int kvrow = tid >> 2;
        const int kc0 = (tid & 3) * 2;
        const float* gkv = g_kv + (size_t)bh*DK*DK + kvrow*64;
        #pragma unroll
        for (int j = 0; j < 2; ++j) {
            const int c = kc0 + j;
            const float4 f0 = *(const float4*)(gkv + c*8);
            const float4 f1 = *(const float4*)(gkv + c*8 + 4);
            uint4 hv;
            hv.x = (uint32_t)__half_as_ushort(__float2half(f0.x))
                 | ((uint32_t)__half_as_ushort(__float2half(f0.y)) << 16);
            hv.y = (uint32_t)__half_as_ushort(__float2half(f0.z))
                 | ((uint32_t)__half_as_ushort(__float2half(f0.w)) << 16);
            hv.z = (uint32_t)__half_as_ushort(__float2half(f1.x))
                 | ((uint32_t)__half_as_ushort(__float2half(f1.y)) << 16);
            hv.w = (uint32_t)__half_as_ushort(__float2half(f1.z))
                 | ((uint32_t)__half_as_ushort(__float2half(f1.w)) << 16);
            const uint32_t ph = (uint32_t)((c ^ (kvrow & 7)) << 4);
            *(uint4*)(smem + AT_KV + kvrow*128 + ph) = hv;
        }
        if (tid < 64) ksum_s[tid] = g_ksum[bh*DK + tid];
        cp_wait<0>();
        __syncthreads();
    }

    if (tid < 128) {
        const int row = tid;
        float s = 0.0f;
        #pragma unroll 16
        for (int d = 0; d < 64; ++d) {
            const int off = row*128 + (((d >> 3) ^ (row & 7)) << 4) + (d & 7)*2;
            s += __half2float(*(const __half*)(smem + AT_Q + off)) * ksum_s[d];
        }
        dens_s[row] = s + 1e-6f;
    }
    __syncthreads();

    int arow[2]; uint32_t aswz[2];
    #pragma unroll
    for (int mt = 0; mt < 2; ++mt) {
        arow[mt] = wm + (l & 15) + mt*16;
        aswz[mt] = (uint32_t)(arow[mt] & 7);
    }
    uint32_t boff[2];
    {
        const int brow = (l & 7) + ((l >> 3) & 1) * 8;
        #pragma unroll
        for (int ng = 0; ng < 2; ++ng) {
            const uint32_t bch = (uint32_t)((wn >> 3) + ng*2 + ((l >> 4) & 1));
            boff[ng] = (uint32_t)(brow * 128) + ((bch ^ (uint32_t)(l & 7)) << 4);
        }
    }

    float acc[8][4];
    #pragma unroll
    for (int i = 0; i < 8; ++i)
        #pragma unroll
        for (int j = 0; j < 4; ++j) acc[i][j] = 0.0f;

    #pragma unroll
    for (int ks = 0; ks < 4; ++ks) {
        uint32_t ah[2][4], bhf[2][4];
        #pragma unroll
        for (int mt = 0; mt < 2; ++mt) {
            const uint32_t ach = (uint32_t)(ks*2 + (l >> 4));
            const uint32_t ao = (uint32_t)(arow[mt]*128) + ((ach ^ aswz[mt]) << 4);
            ldsm_x4(ah[mt], sbase + AT_Q + ao);
        }
        #pragma unroll
        for (int ng = 0; ng < 2; ++ng) {
            const uint32_t ko = (uint32_t)(ks * 2048);
            ldsm_x4_t(bhf[ng], sbase + AT_KV + ko + boff[ng]);
        }
        #pragma unroll
        for (int mt = 0; mt < 2; ++mt)
            #pragma unroll
            for (int g = 0; g < 4; ++g)
                mma_f16(acc[mt*4+g], ah[mt], &bhf[g >> 1][(g & 1)*2]);
    }

    #pragma unroll
    for (int mt = 0; mt < 2; ++mt)
        #pragma unroll
        for (int g = 0; g < 4; ++g) {
            const int t = mt*4 + g;
            const int lr = wm + mt*16 + (l >> 2);
            const int f = wn + g*8 + (l & 3)*2;
            const float inv1 = 1.0f / dens_s[lr];
            const float inv2 = 1.0f / dens_s[lr + 8];
            ushort2 h0, h1;
            h0.x = __half_as_ushort(__float2half(acc[t][0]*inv1));
            h0.y = __half_as_ushort(__float2half(acc[t][1]*inv1));
            h1.x = __half_as_ushort(__float2half(acc[t][2]*inv2));
            h1.y = __half_as_ushort(__float2half(acc[t][3]*inv2));
            const size_t o1 = (size_t)(b*SEQ + n0 + lr) * DMODEL + hh*64 + f;
            const size_t o2 = o1 + (size_t)8 * DMODEL;
            *(ushort2*)(g_ahi + o1) = h0;
            *(ushort2*)(g_ahi + o2) = h1;
        }
}

// ---------------------------------------------------------------------------
extern "C" void kernel_launch(void* const* d_in, const int* in_sizes, int n_in,
                              void* d_out, int out_size)
{
    const float* x    = (const float*)d_in[0];
    const float* wqkv = (const float*)d_in[1];
    const float* wo   = (const float*)d_in[2];
    float* out = (float*)d_out;

    __half *xh, *ahi, *wqh, *woh, *qkh;
    cudaGetSymbolAddress((void**)&xh, g_xh);
    cudaGetSymbolAddress((void**)&ahi, g_ahi);
    cudaGetSymbolAddress((void**)&wqh, g_wqh);
    cudaGetSymbolAddress((void**)&woh, g_woh);
    cudaGetSymbolAddress((void**)&qkh, g_qkh);

    cudaFuncSetAttribute(hmma_kernel<true, true>,
        cudaFuncAttributeMaxDynamicSharedMemorySize, HS_TOTAL);
    cudaFuncSetAttribute(hmma_kernel<false, false>,
        cudaFuncAttributeMaxDynamicSharedMemorySize, HS_TOTAL);
    cudaFuncSetAttribute(kv_tc_kernel,
        cudaFuncAttributeMaxDynamicSharedMemorySize, KV_SMEM);
    cudaFuncSetAttribute(attn_tc_kernel,
        cudaFuncAttributeMaxDynamicSharedMemorySize, AT_SMEM);

    // 1) convert x to single fp16; weights to single fp16 (transposed)
    {
        int n4 = MTOT * DMODEL / 4;
        cvt_kernel<<<(n4 + 255)/256, 256>>>(x, xh, n4);
    }
    tsingle_kernel<<<(DMODEL*QKVN + 255)/256, 256>>>(wqkv, wqh, DMODEL, QKVN);
    tsingle_kernel<<<(DMODEL*DMODEL + 255)/256, 256>>>(wo, woh, DMODEL, DMODEL);

    // 2) QKV projection (1-term); epilogue: elu+1 on q,k; single fp16 out
    hmma_kernel<true, true><<<dim3(QKVN/128, MTOT/128), 256, HS_TOTAL>>>(
        xh, wqh, nullptr, qkh, QKVN, DMODEL);

    // 3) zero accumulators
    zero_kv_kernel<<<(BATCH*NH*DK*DK + 255)/256, 256>>>();

    // 4) kv = k^T v (+ksum) via tensor cores, split-K atomics
    kv_tc_kernel<<<dim3(BATCH*NH, 16), 256, KV_SMEM>>>();

    // 5) attn = (q @ kv) / (q . ksum + 1e-6) -> single fp16 (kvsplit folded in)
    attn_tc_kernel<<<dim3(SEQ/128, BATCH*NH), 256, AT_SMEM>>>();

    // 6) output projection (1-term)
    hmma_kernel<false, false><<<dim3(DMODEL/128, MTOT/128), 256, HS_TOTAL>>>(
        ahi, woh, out, nullptr, DMODEL, DMODEL);
}

// round 17
// speedup vs baseline: 1.0343x; 1.0312x over previous
#include <cuda_runtime.h>
#include <cuda_fp16.h>
#include <cstdint>
#include <math.h>

#define BATCH 4
#define SEQ   8192
#define DMODEL 1024
#define NH    16
#define DK    64
#define QKVN  (3*DMODEL)
#define MTOT  (BATCH*SEQ)

// ---------------------------------------------------------------------------
// Scratch (__device__ globals; allocation-free rule)
// All GEMM operands single fp16; fp32 accumulation everywhere.
// ---------------------------------------------------------------------------
__device__ __half g_xh[(size_t)MTOT*DMODEL];     // x single fp16
__device__ __half g_qkh[(size_t)MTOT*QKVN];      // qkv fp16 (q,k activated)
__device__ __half g_ahi[(size_t)MTOT*DMODEL];    // attn single fp16
__device__ __half g_wqh[(size_t)QKVN*DMODEL];    // w_qkv^T single fp16
__device__ __half g_woh[(size_t)DMODEL*DMODEL];  // w_o^T single fp16
__device__ float g_kv[BATCH*NH*DK*DK];           // fp32 accum [bh][d][f]
__device__ float g_ksum[BATCH*NH*DK];

// ---------------------------------------------------------------------------
// Helpers (baseline PTX only: must assemble at target sm_103)
// ---------------------------------------------------------------------------
__device__ __forceinline__ uint32_t smem_u32(const void* p) {
    uint32_t a;
    asm("{ .reg .u64 t; cvta.to.shared.u64 t, %1; cvt.u32.u64 %0, t; }" : "=r"(a) : "l"(p));
    return a;
}
__device__ __forceinline__ void cp_async16(uint32_t saddr, const void* gaddr) {
    asm volatile("cp.async.cg.shared.global [%0], [%1], 16;" :: "r"(saddr), "l"(gaddr));
}
__device__ __forceinline__ void cp_commit() {
    asm volatile("cp.async.commit_group;" ::: "memory");
}
template<int N>
__device__ __forceinline__ void cp_wait() {
    asm volatile("cp.async.wait_group %0;" :: "n"(N) : "memory");
}
__device__ __forceinline__ void ldsm_x4(uint32_t* r, uint32_t addr) {
    asm volatile("ldmatrix.sync.aligned.m8n8.x4.shared.b16 {%0,%1,%2,%3}, [%4];"
        : "=r"(r[0]), "=r"(r[1]), "=r"(r[2]), "=r"(r[3]) : "r"(addr));
}
__device__ __forceinline__ void ldsm_x4_t(uint32_t* r, uint32_t addr) {
    asm volatile("ldmatrix.sync.aligned.m8n8.x4.trans.shared.b16 {%0,%1,%2,%3}, [%4];"
        : "=r"(r[0]), "=r"(r[1]), "=r"(r[2]), "=r"(r[3]) : "r"(addr));
}
__device__ __forceinline__ void mma_f16(float* c, const uint32_t* a, const uint32_t* b) {
    asm volatile(
        "mma.sync.aligned.m16n8k16.row.col.f32.f16.f16.f32 "
        "{%0,%1,%2,%3}, {%4,%5,%6,%7}, {%8,%9}, {%0,%1,%2,%3};"
        : "+f"(c[0]), "+f"(c[1]), "+f"(c[2]), "+f"(c[3])
        : "r"(a[0]), "r"(a[1]), "r"(a[2]), "r"(a[3]), "r"(b[0]), "r"(b[1]));
}

// ---------------------------------------------------------------------------
// Convert fp32 -> single fp16 (coalesced)
// ---------------------------------------------------------------------------
__global__ void __launch_bounds__(256) cvt_kernel(
    const float* __restrict__ src, __half* __restrict__ dst, int n4)
{
    int i = blockIdx.x * 256 + threadIdx.x;
    if (i >= n4) return;
    float4 v = ((const float4*)src)[i];
    ushort4 hv;
    hv.x = __half_as_ushort(__float2half(v.x));
    hv.y = __half_as_ushort(__float2half(v.y));
    hv.z = __half_as_ushort(__float2half(v.z));
    hv.w = __half_as_ushort(__float2half(v.w));
    ((ushort4*)dst)[i] = hv;
}

// ---------------------------------------------------------------------------
// Tiled transpose + round: w [K][N] fp32 -> wT [N][K] fp16.
// 32x32 smem tile (stride 33), coalesced reads AND writes.
// Block 32x8; grid (N/32, K/32).
// ---------------------------------------------------------------------------
__global__ void __launch_bounds__(256) ttrans_kernel(
    const float* __restrict__ w, __half* __restrict__ o, int K, int N)
{
    __shared__ float t[32][33];
    const int n0 = blockIdx.x * 32;
    const int k0 = blockIdx.y * 32;
    const int tx = threadIdx.x;        // 0..31
    const int ty = threadIdx.y;        // 0..7
    #pragma unroll
    for (int i = 0; i < 32; i += 8)
        t[ty + i][tx] = w[(size_t)(k0 + ty + i) * N + n0 + tx];
    __syncthreads();
    #pragma unroll
    for (int i = 0; i < 32; i += 8)
        o[(size_t)(n0 + ty + i) * K + k0 + tx] = __float2half(t[tx][ty + i]);
}

// ---------------------------------------------------------------------------
// mma.sync fp16 1-term GEMM: C = A[M,K] @ B^T (both single fp16, [N][K] B).
// BM=BN=128, BK=32, 256 threads (8 warps 4m x 2n, warp tile 32x64),
// 4-stage cp.async pipeline, XOR-swizzled smem, 2 CTAs/SM.   [R14 config]
// GEMM1 (ACT=1,SPLIT=1): elu+1 on cols<2048, output single fp16.
// GEMM2 (ACT=0,SPLIT=0): fp32 output.
// ---------------------------------------------------------------------------
#define TILE_B (128*64)            // 8192 B per operand tile
#define STAGE_B (2*TILE_B)         // A|B = 16384 B
#define OFF_A 0
#define OFF_B TILE_B
#define NSTAGE 4
#define HS_TOTAL (NSTAGE*STAGE_B)  // 65536 B

template<bool ACT, bool SPLIT>
__global__ void __launch_bounds__(256, 2)
hmma_kernel(const __half* __restrict__ A, const __half* __restrict__ B,
            float* __restrict__ Cf, __half* __restrict__ Chi, int ldc, int K)
{
    extern __shared__ __align__(128) char smem[];
    const uint32_t sbase = smem_u32(smem);
    const int tid = threadIdx.x;
    const int wid = tid >> 5, l = tid & 31;
    const int n0 = blockIdx.x * 128;
    const int m0 = blockIdx.y * 128;
    const int wm = (wid & 3) * 32;
    const int wn = (wid >> 2) * 64;

    const int lrow = tid >> 1;
    const int c0   = (tid & 1) * 2;
    const int lsw  = (lrow >> 1) & 3;
    const char* gA = (const char*)(A + (size_t)(m0 + lrow) * K);
    const char* gB = (const char*)(B + (size_t)(n0 + lrow) * K);
    const uint32_t sd0 = sbase + lrow * 64 + (uint32_t)((c0 ^ lsw) << 4);
    const uint32_t sd1 = sbase + lrow * 64 + (uint32_t)(((c0 + 1) ^ lsw) << 4);

    const int nkt = K >> 5;

    auto load_stage = [&](int kt, int buf) {
        const uint32_t bo = (uint32_t)(buf * STAGE_B);
        const int goff = kt * 64;
        cp_async16(sd0 + bo + OFF_A, gA + goff + c0 * 16);
        cp_async16(sd1 + bo + OFF_A, gA + goff + c0 * 16 + 16);
        cp_async16(sd0 + bo + OFF_B, gB + goff + c0 * 16);
        cp_async16(sd1 + bo + OFF_B, gB + goff + c0 * 16 + 16);
    };

    load_stage(0, 0); cp_commit();
    load_stage(1, 1); cp_commit();
    load_stage(2, 2); cp_commit();

    float acc[16][4];
    #pragma unroll
    for (int i = 0; i < 16; ++i)
        #pragma unroll
        for (int j = 0; j < 4; ++j) acc[i][j] = 0.0f;

    uint32_t aoff[2][2], boff[2][4];
    {
        const uint32_t caA = (uint32_t)(l >> 4);
        const uint32_t caB = (uint32_t)((l >> 3) & 1);
        #pragma unroll
        for (int mt = 0; mt < 2; ++mt) {
            const int r = wm + (l & 15) + mt * 16;
            const uint32_t sw = (uint32_t)((r >> 1) & 3);
            #pragma unroll
            for (int kk = 0; kk < 2; ++kk)
                aoff[kk][mt] = (uint32_t)(r * 64) + (((kk * 2 + caA) ^ sw) << 4);
        }
        #pragma unroll
        for (int ng = 0; ng < 4; ++ng) {
            const int r = wn + ((l >> 4) & 1) * 8 + (l & 7) + ng * 16;
            const uint32_t sw = (uint32_t)((r >> 1) & 3);
            #pragma unroll
            for (int kk = 0; kk < 2; ++kk)
                boff[kk][ng] = (uint32_t)(r * 64) + (((kk * 2 + caB) ^ sw) << 4);
        }
    }

    int buf = 0, lbuf = NSTAGE - 1;
    #pragma unroll 1
    for (int kt = 0; kt < nkt; ++kt) {
        cp_wait<NSTAGE - 2>();
        __syncthreads();
        if (kt + NSTAGE - 1 < nkt) { load_stage(kt + NSTAGE - 1, lbuf); }
        cp_commit();

        const uint32_t sb = sbase + buf * STAGE_B;
        #pragma unroll
        for (int kk = 0; kk < 2; ++kk) {
            uint32_t ah[2][4], bh[4][4];
            #pragma unroll
            for (int mt = 0; mt < 2; ++mt)
                ldsm_x4(ah[mt], sb + OFF_A + aoff[kk][mt]);
            #pragma unroll
            for (int ng = 0; ng < 4; ++ng)
                ldsm_x4(bh[ng], sb + OFF_B + boff[kk][ng]);
            #pragma unroll
            for (int mt = 0; mt < 2; ++mt)
                #pragma unroll
                for (int nt = 0; nt < 8; ++nt)
                    mma_f16(acc[mt * 8 + nt], ah[mt], &bh[nt >> 1][(nt & 1) * 2]);
        }
        buf  = (buf  == NSTAGE - 1) ? 0 : buf + 1;
        lbuf = (lbuf == NSTAGE - 1) ? 0 : lbuf + 1;
    }

    const bool doact = ACT && (n0 < 2048);
    const int erow = m0 + wm + (l >> 2);
    const int ecol = n0 + wn + (l & 3) * 2;
    #pragma unroll
    for (int mt = 0; mt < 2; ++mt)
        #pragma unroll
        for (int nt = 0; nt < 8; ++nt) {
            float v0 = acc[mt*8+nt][0], v1 = acc[mt*8+nt][1];
            float v2 = acc[mt*8+nt][2], v3 = acc[mt*8+nt][3];
            if (doact) {
                v0 = (v0 > 0.f) ? v0 + 1.f : expf(v0);
                v1 = (v1 > 0.f) ? v1 + 1.f : expf(v1);
                v2 = (v2 > 0.f) ? v2 + 1.f : expf(v2);
                v3 = (v3 > 0.f) ? v3 + 1.f : expf(v3);
            }
            const int r = erow + mt * 16;
            const int cc = ecol + nt * 8;
            if (SPLIT) {
                ushort2 h0, h1;
                h0.x = __half_as_ushort(__float2half(v0));
                h0.y = __half_as_ushort(__float2half(v1));
                h1.x = __half_as_ushort(__float2half(v2));
                h1.y = __half_as_ushort(__float2half(v3));
                *(ushort2*)(Chi + (size_t)r * ldc + cc) = h0;
                *(ushort2*)(Chi + (size_t)(r + 8) * ldc + cc) = h1;
            } else {
                float2 o0; o0.x = v0; o0.y = v1;
                float2 o1; o1.x = v2; o1.y = v3;
                *(float2*)(Cf + (size_t)r * ldc + cc) = o0;
                *(float2*)(Cf + (size_t)(r + 8) * ldc + cc) = o1;
            }
        }
}

// ---------------------------------------------------------------------------
// Zero kv/ksum accumulators
// ---------------------------------------------------------------------------
__global__ void zero_kv_kernel() {
    int i = blockIdx.x * 256 + threadIdx.x;
    if (i < BATCH*NH*DK*DK) g_kv[i] = 0.0f;
    if (i < BATCH*NH*DK)    g_ksum[i] = 0.0f;
}

// ---------------------------------------------------------------------------
// kv GEMM (tensor): C[bh][d][f] += k^T @ v over 512-row split; ksum SIMT.
// ---------------------------------------------------------------------------
#define KV_TILE_B (64*128)          // 8192
#define KV_STAGE_B (2*KV_TILE_B)    // k|v = 16384
#define KV_SMEM (2*KV_STAGE_B)      // 32768

__global__ void __launch_bounds__(256, 2) kv_tc_kernel()
{
    extern __shared__ __align__(128) char smem[];
    const uint32_t sbase = smem_u32(smem);
    const int tid = threadIdx.x;
    const int wid = tid >> 5, l = tid & 31;
    const int bh = blockIdx.x;
    const int b = bh >> 4, h = bh & 15;
    const int n0 = blockIdx.y * 512;
    const int wm = (wid & 1) * 32;      // d offset
    const int wn = (wid >> 1) * 16;     // f offset

    const int lrow = tid >> 2;
    const int lc0 = (tid & 3) * 2;
    const uint32_t sw0 = (uint32_t)((lc0 ^ (lrow & 7)) << 4);
    const uint32_t sw1 = (uint32_t)(((lc0 + 1) ^ (lrow & 7)) << 4);
    const uint32_t sdr = sbase + (uint32_t)(lrow * 128);

    auto load_chunk = [&](int c, int buf) {
        const size_t gr = (size_t)(b*SEQ + n0 + c*64 + lrow) * QKVN + h*64;
        const __half* srcK = g_qkh + gr + 1024;
        const __half* srcV = g_qkh + gr + 2048;
        const uint32_t sb = sdr + buf * KV_STAGE_B;
        cp_async16(sb + sw0, srcK + lc0*8);
        cp_async16(sb + sw1, srcK + lc0*8 + 8);
        cp_async16(sb + KV_TILE_B + sw0, srcV + lc0*8);
        cp_async16(sb + KV_TILE_B + sw1, srcV + lc0*8 + 8);
    };

    uint32_t aoff[2], boff;
    {
        const int arow = (l & 7) + ((l >> 4) & 1) * 8;
        #pragma unroll
        for (int mt = 0; mt < 2; ++mt) {
            const uint32_t ach = (uint32_t)((wm >> 3) + mt * 2 + ((l >> 3) & 1));
            aoff[mt] = (uint32_t)(arow * 128) + ((ach ^ (uint32_t)(l & 7)) << 4);
        }
        const int brow = (l & 7) + ((l >> 3) & 1) * 8;
        const uint32_t bch = (uint32_t)((wn >> 3) + ((l >> 4) & 1));
        boff = (uint32_t)(brow * 128) + ((bch ^ (uint32_t)(l & 7)) << 4);
    }

    float acc[4][4];
    #pragma unroll
    for (int i = 0; i < 4; ++i)
        #pragma unroll
        for (int j = 0; j < 4; ++j) acc[i][j] = 0.0f;
    float ksacc = 0.0f;
    const int kd = tid & 63;
    const int kr0 = (tid >> 6) * 16;

    load_chunk(0, 0); cp_commit();

    #pragma unroll 1
    for (int c = 0; c < 8; ++c) {
        cp_wait<0>();
        __syncthreads();
        if (c < 7) { load_chunk(c + 1, (c + 1) & 1); }
        cp_commit();

        const int bufo = (c & 1) * KV_STAGE_B;
        const uint32_t sb = sbase + bufo;

        #pragma unroll
        for (int i = 0; i < 16; ++i) {
            const int row = kr0 + i;
            const int off = bufo + row*128 + (((kd >> 3) ^ (row & 7)) << 4) + (kd & 7)*2;
            ksacc += __half2float(*(const __half*)(smem + off));
        }

        #pragma unroll
        for (int ks = 0; ks < 4; ++ks) {
            const uint32_t ko = (uint32_t)(ks * 2048);
            uint32_t ah[2][4], bhf[4];
            #pragma unroll
            for (int mt = 0; mt < 2; ++mt)
                ldsm_x4_t(ah[mt], sb + ko + aoff[mt]);
            ldsm_x4_t(bhf, sb + KV_TILE_B + ko + boff);
            #pragma unroll
            for (int mt = 0; mt < 2; ++mt)
                #pragma unroll
                for (int ng = 0; ng < 2; ++ng)
                    mma_f16(acc[mt*2+ng], ah[mt], &bhf[ng*2]);
        }
    }

    #pragma unroll
    for (int mt = 0; mt < 2; ++mt)
        #pragma unroll
        for (int ng = 0; ng < 2; ++ng) {
            const int t = mt*2 + ng;
            const int d = wm + mt*16 + (l >> 2);
            const int f = wn + ng*8 + (l & 3)*2;
            float* dst = g_kv + ((size_t)bh*DK + d)*DK + f;
            atomicAdd(dst,     acc[t][0]);
            atomicAdd(dst + 1, acc[t][1]);
            float* dst2 = dst + 8*DK;
            atomicAdd(dst2,     acc[t][2]);
            atomicAdd(dst2 + 1, acc[t][3]);
        }
    atomicAdd(g_ksum + bh*DK + kd, ksacc);
}

// ---------------------------------------------------------------------------
// attn GEMM (tensor): attn[n,f] = (q @ kv) / (q . ksum + 1e-6)
// kv loaded fp32 from g_kv and converted to fp16 during smem staging.
// ---------------------------------------------------------------------------
#define AT_Q 0
#define AT_KV 16384
#define AT_KSUM 24576
#define AT_DENS 24832
#define AT_SMEM 25344

__global__ void __launch_bounds__(256, 2) attn_tc_kernel()
{
    extern __shared__ __align__(128) char smem[];
    const uint32_t sbase = smem_u32(smem);
    float* ksum_s = (float*)(smem + AT_KSUM);
    float* dens_s = (float*)(smem + AT_DENS);
    const int tid = threadIdx.x;
    const int wid = tid >> 5, l = tid & 31;
    const int n0 = blockIdx.x * 128;
    const int bh = blockIdx.y;
    const int b = bh >> 4, hh = bh & 15;
    const int wm = (wid & 3) * 32;
    const int wn = (wid >> 2) * 32;

    {
        const int qrow = tid >> 1;
        const int qc0 = (tid & 1) * 4;
        const size_t gq = (size_t)(b*SEQ + n0 + qrow) * QKVN + hh*64;
        #pragma unroll
        for (int j = 0; j < 4; ++j) {
            const int c = qc0 + j;
            const uint32_t ph = (uint32_t)((c ^ (qrow & 7)) << 4);
            cp_async16(sbase + AT_Q + qrow*128 + ph, g_qkh + gq + c*8);
        }
        cp_commit();

        const int kvrow = tid >> 2;
        const int kc0 = (tid & 3) * 2;
        const float* gkv = g_kv + (size_t)bh*DK*DK + kvrow*64;
        #pragma unroll
        for (int j = 0; j < 2; ++j) {
            const int c = kc0 + j;
            const float4 f0 = *(const float4*)(gkv + c*8);
            const float4 f1 = *(const float4*)(gkv + c*8 + 4);
            uint4 hv;
            hv.x = (uint32_t)__half_as_ushort(__float2half(f0.x))
                 | ((uint32_t)__half_as_ushort(__float2half(f0.y)) << 16);
            hv.y = (uint32_t)__half_as_ushort(__float2half(f0.z))
                 | ((uint32_t)__half_as_ushort(__float2half(f0.w)) << 16);
            hv.z = (uint32_t)__half_as_ushort(__float2half(f1.x))
                 | ((uint32_t)__half_as_ushort(__float2half(f1.y)) << 16);
            hv.w = (uint32_t)__half_as_ushort(__float2half(f1.z))
                 | ((uint32_t)__half_as_ushort(__float2half(f1.w)) << 16);
            const uint32_t ph = (uint32_t)((c ^ (kvrow & 7)) << 4);
            *(uint4*)(smem + AT_KV + kvrow*128 + ph) = hv;
        }
        if (tid < 64) ksum_s[tid] = g_ksum[bh*DK + tid];
        cp_wait<0>();
        __syncthreads();
    }

    if (tid < 128) {
        const int row = tid;
        float s = 0.0f;
        #pragma unroll 16
        for (int d = 0; d < 64; ++d) {
            const int off = row*128 + (((d >> 3) ^ (row & 7)) << 4) + (d & 7)*2;
            s += __half2float(*(const __half*)(smem + AT_Q + off)) * ksum_s[d];
        }
        dens_s[row] = s + 1e-6f;
    }
    __syncthreads();

    int arow[2]; uint32_t aswz[2];
    #pragma unroll
    for (int mt = 0; mt < 2; ++mt) {
        arow[mt] = wm + (l & 15) + mt*16;
        aswz[mt] = (uint32_t)(arow[mt] & 7);
    }
    uint32_t boff[2];
    {
        const int brow = (l & 7) + ((l >> 3) & 1) * 8;
        #pragma unroll
        for (int ng = 0; ng < 2; ++ng) {
            const uint32_t bch = (uint32_t)((wn >> 3) + ng*2 + ((l >> 4) & 1));
            boff[ng] = (uint32_t)(brow * 128) + ((bch ^ (uint32_t)(l & 7)) << 4);
        }
    }

    float acc[8][4];
    #pragma unroll
    for (int i = 0; i < 8; ++i)
        #pragma unroll
        for (int j = 0; j < 4; ++j) acc[i][j] = 0.0f;

    #pragma unroll
    for (int ks = 0; ks < 4; ++ks) {
        uint32_t ah[2][4], bhf[2][4];
        #pragma unroll
        for (int mt = 0; mt < 2; ++mt) {
            const uint32_t ach = (uint32_t)(ks*2 + (l >> 4));
            const uint32_t ao = (uint32_t)(arow[mt]*128) + ((ach ^ aswz[mt]) << 4);
            ldsm_x4(ah[mt], sbase + AT_Q + ao);
        }
        #pragma unroll
        for (int ng = 0; ng < 2; ++ng) {
            const uint32_t ko = (uint32_t)(ks * 2048);
            ldsm_x4_t(bhf[ng], sbase + AT_KV + ko + boff[ng]);
        }
        #pragma unroll
        for (int mt = 0; mt < 2; ++mt)
            #pragma unroll
            for (int g = 0; g < 4; ++g)
                mma_f16(acc[mt*4+g], ah[mt], &bhf[g >> 1][(g & 1)*2]);
    }

    #pragma unroll
    for (int mt = 0; mt < 2; ++mt)
        #pragma unroll
        for (int g = 0; g < 4; ++g) {
            const int t = mt*4 + g;
            const int lr = wm + mt*16 + (l >> 2);
            const int f = wn + g*8 + (l & 3)*2;
            const float inv1 = 1.0f / dens_s[lr];
            const float inv2 = 1.0f / dens_s[lr + 8];
            ushort2 h0, h1;
            h0.x = __half_as_ushort(__float2half(acc[t][0]*inv1));
            h0.y = __half_as_ushort(__float2half(acc[t][1]*inv1));
            h1.x = __half_as_ushort(__float2half(acc[t][2]*inv2));
            h1.y = __half_as_ushort(__float2half(acc[t][3]*inv2));
            const size_t o1 = (size_t)(b*SEQ + n0 + lr) * DMODEL + hh*64 + f;
            const size_t o2 = o1 + (size_t)8 * DMODEL;
            *(ushort2*)(g_ahi + o1) = h0;
            *(ushort2*)(g_ahi + o2) = h1;
        }
}

// ---------------------------------------------------------------------------
extern "C" void kernel_launch(void* const* d_in, const int* in_sizes, int n_in,
                              void* d_out, int out_size)
{
    const float* x    = (const float*)d_in[0];
    const float* wqkv = (const float*)d_in[1];
    const float* wo   = (const float*)d_in[2];
    float* out = (float*)d_out;

    __half *xh, *ahi, *wqh, *woh, *qkh;
    cudaGetSymbolAddress((void**)&xh, g_xh);
    cudaGetSymbolAddress((void**)&ahi, g_ahi);
    cudaGetSymbolAddress((void**)&wqh, g_wqh);
    cudaGetSymbolAddress((void**)&woh, g_woh);
    cudaGetSymbolAddress((void**)&qkh, g_qkh);

    cudaFuncSetAttribute(hmma_kernel<true, true>,
        cudaFuncAttributeMaxDynamicSharedMemorySize, HS_TOTAL);
    cudaFuncSetAttribute(hmma_kernel<false, false>,
        cudaFuncAttributeMaxDynamicSharedMemorySize, HS_TOTAL);
    cudaFuncSetAttribute(kv_tc_kernel,
        cudaFuncAttributeMaxDynamicSharedMemorySize, KV_SMEM);
    cudaFuncSetAttribute(attn_tc_kernel,
        cudaFuncAttributeMaxDynamicSharedMemorySize, AT_SMEM);

    // 1) convert x; tiled-transpose+round weights (coalesced both ways)
    {
        int n4 = MTOT * DMODEL / 4;
        cvt_kernel<<<(n4 + 255)/256, 256>>>(x, xh, n4);
    }
    ttrans_kernel<<<dim3(QKVN/32, DMODEL/32), dim3(32, 8)>>>(wqkv, wqh, DMODEL, QKVN);
    ttrans_kernel<<<dim3(DMODEL/32, DMODEL/32), dim3(32, 8)>>>(wo, woh, DMODEL, DMODEL);

    // 2) QKV projection (1-term); epilogue: elu+1 on q,k; single fp16 out
    hmma_kernel<true, true><<<dim3(QKVN/128, MTOT/128), 256, HS_TOTAL>>>(
        xh, wqh, nullptr, qkh, QKVN, DMODEL);

    // 3) zero accumulators
    zero_kv_kernel<<<(BATCH*NH*DK*DK + 255)/256, 256>>>();

    // 4) kv = k^T v (+ksum) via tensor cores, split-K atomics
    kv_tc_kernel<<<dim3(BATCH*NH, 16), 256, KV_SMEM>>>();

    // 5) attn = (q @ kv) / (q . ksum + 1e-6) -> single fp16 (kvsplit folded)
    attn_tc_kernel<<<dim3(SEQ/128, BATCH*NH), 256, AT_SMEM>>>();

    // 6) output projection (1-term)
    hmma_kernel<false, false><<<dim3(DMODEL/128, MTOT/128), 256, HS_TOTAL>>>(
        ahi, woh, out, nullptr, DMODEL, DMODEL);
}